// round 6
// baseline (speedup 1.0000x reference)
#include <cuda_runtime.h>
#include <math_constants.h>

// Chamfer distance: B=8, N=M=4096, D=2 on sm_100a — single fused kernel.
// Work item = (dbsplit, pair, qtile): 8 x 16 x 4 = 512 blocks of 256 threads.
// Each thread handles Q=4 queries against a 512-point DB chunk staged in smem
// as packed pairs (u0,u1) = -2*t and h = |t|^2; score via fma.rn.f32x2
// (2 points/instr), mins via scalar FMNMX (alu pipe, runs parallel to fma).
// Per-query clamped partial d^2 -> g_pmin[pair][qi][split]; the last-arriving
// block of each pair finalizes (min over 8 splits, sqrt, sum, one atomicAdd).
// Counters self-reset for graph replay.

#define NPTS    4096
#define THREADS 256
#define Q       4
#define DBSPLIT 8
#define DBCHUNK (NPTS / DBSPLIT)                 // 512 points
#define QTILES  (NPTS / (THREADS * Q))           // 4
#define NPAIRS  16

__device__ float g_pmin[NPAIRS * NPTS * DBSPLIT];  // [pair][qi][split], 2 MB
__device__ int   g_count[NPAIRS];                   // zero-init; self-reset

union F2 { unsigned long long u; float2 f; };

__device__ __forceinline__ unsigned long long ffma2(unsigned long long a,
                                                    unsigned long long b,
                                                    unsigned long long c)
{
    unsigned long long d;
    asm("fma.rn.f32x2 %0, %1, %2, %3;" : "=l"(d) : "l"(a), "l"(b), "l"(c));
    return d;
}

__device__ __forceinline__ unsigned long long bcast2(float v)
{
    unsigned long long r;
    asm("mov.b64 %0, {%1, %1};" : "=l"(r) : "f"(v));
    return r;
}

__global__ __launch_bounds__(THREADS)
void chamfer_fused(const float* __restrict__ x, const float* __restrict__ tgt,
                   float* __restrict__ out)
{
    __shared__ __align__(16) float4 s_uv[DBCHUNK / 2];   // 4 KB: (u0a,u0b,u1a,u1b)
    __shared__ __align__(16) float2 s_h[DBCHUNK / 2];    // 2 KB: (ha,hb)
    __shared__ float s_warp[THREADS / 32];
    __shared__ int   s_last;

    const int blk   = blockIdx.x;
    const int qtile = blk & (QTILES - 1);
    const int pair  = (blk >> 2) & (NPAIRS - 1);
    const int split = blk >> 6;
    const int dir   = pair & 1;
    const int b     = pair >> 1;

    const float* q_base = (dir ? tgt : x) + (size_t)b * NPTS * 2;
    const float* d_base = (dir ? x : tgt) + (size_t)b * NPTS * 2
                          + (size_t)split * DBCHUNK * 2;

    // Stage DB chunk: 256 point-pairs, exactly 1 per thread.
    {
        const float4* db4 = (const float4*)d_base;
        int p = threadIdx.x;                    // DBCHUNK/2 == THREADS
        float4 t = db4[p];                      // (t0x,t0y,t1x,t1y)
        s_uv[p] = make_float4(-2.0f * t.x, -2.0f * t.z,
                              -2.0f * t.y, -2.0f * t.w);
        s_h[p]  = make_float2(fmaf(t.x, t.x, t.y * t.y),
                              fmaf(t.z, t.z, t.w * t.w));
    }
    __syncthreads();

    // Q=4 queries per thread.
    int qi[Q];
    unsigned long long qxx[Q], qyy[Q];
    float q2[Q];
    #pragma unroll
    for (int k = 0; k < Q; k++) {
        qi[k] = qtile * (THREADS * Q) + k * THREADS + threadIdx.x;
        float2 q = ((const float2*)q_base)[qi[k]];
        qxx[k] = bcast2(q.x);
        qyy[k] = bcast2(q.y);
        q2[k]  = fmaf(q.x, q.x, q.y * q.y);
    }

    float mA[Q], mB[Q];
    #pragma unroll
    for (int k = 0; k < Q; k++) { mA[k] = CUDART_INF_F; mB[k] = CUDART_INF_F; }

    const ulonglong2* uvp = (const ulonglong2*)s_uv;  // [p]: (u0pk, u1pk)
    const ulonglong2* hpp = (const ulonglong2*)s_h;   // [i]: h of pts 4i..4i+3

    #pragma unroll 4
    for (int i = 0; i < DBCHUNK / 4; i++) {           // 4 points per iter
        ulonglong2 uvA = uvp[2 * i];
        ulonglong2 uvB = uvp[2 * i + 1];
        ulonglong2 hh  = hpp[i];
        #pragma unroll
        for (int k = 0; k < Q; k++) {
            F2 sA, sB;
            sA.u = ffma2(qxx[k], uvA.x, ffma2(qyy[k], uvA.y, hh.x));
            sB.u = ffma2(qxx[k], uvB.x, ffma2(qyy[k], uvB.y, hh.y));
            mA[k] = fminf(mA[k], sA.f.x);
            mB[k] = fminf(mB[k], sA.f.y);
            mA[k] = fminf(mA[k], sB.f.x);
            mB[k] = fminf(mB[k], sB.f.y);
        }
    }

    // Store clamped partial d^2 (clamp commutes with min across splits).
    #pragma unroll
    for (int k = 0; k < Q; k++) {
        float d2 = fmaxf(fminf(mA[k], mB[k]) + q2[k], 0.0f);
        g_pmin[((size_t)pair * NPTS + qi[k]) * DBSPLIT + split] = d2;
    }

    // Arrival protocol.
    __threadfence();
    __syncthreads();
    if (threadIdx.x == 0)
        s_last = (atomicAdd(&g_count[pair], 1) == DBSPLIT * QTILES - 1);
    __syncthreads();
    if (!s_last) return;

    // Last block of this pair: combine 8 splits, sqrt, sum.
    __threadfence();
    const float4* pm4 = (const float4*)(g_pmin + (size_t)pair * NPTS * DBSPLIT);
    float acc = 0.0f;
    #pragma unroll
    for (int q = threadIdx.x; q < NPTS; q += THREADS) {
        float4 p0 = pm4[2 * q];
        float4 p1 = pm4[2 * q + 1];
        float m = fminf(fminf(fminf(p0.x, p0.y), fminf(p0.z, p0.w)),
                        fminf(fminf(p1.x, p1.y), fminf(p1.z, p1.w)));
        acc += sqrtf(m);
    }

    #pragma unroll
    for (int off = 16; off > 0; off >>= 1)
        acc += __shfl_down_sync(0xFFFFFFFFu, acc, off);
    const int lane = threadIdx.x & 31;
    const int wid  = threadIdx.x >> 5;
    if (lane == 0) s_warp[wid] = acc;
    __syncthreads();
    if (wid == 0) {
        float w = (lane < THREADS / 32) ? s_warp[lane] : 0.0f;
        #pragma unroll
        for (int off = 4; off > 0; off >>= 1)
            w += __shfl_down_sync(0xFFFFFFFFu, w, off);
        if (lane == 0) {
            atomicAdd(out, w * (1.0f / 32768.0f));
            g_count[pair] = 0;               // reset for next graph replay
        }
    }
}

extern "C" void kernel_launch(void* const* d_in, const int* in_sizes, int n_in,
                              void* d_out, int out_size)
{
    const float* x   = (const float*)d_in[0];   // [8,4096,2] f32
    const float* tgt = (const float*)d_in[1];   // [8,4096,2] f32
    float* out = (float*)d_out;

    (void)in_sizes; (void)n_in; (void)out_size;

    cudaMemsetAsync(d_out, 0, sizeof(float));
    chamfer_fused<<<DBSPLIT * NPAIRS * QTILES, THREADS>>>(x, tgt, out);
}

// round 7
// speedup vs baseline: 1.0492x; 1.0492x over previous
#include <cuda_runtime.h>
#include <math_constants.h>

// Chamfer distance: B=8, N=M=4096, D=2 on sm_100a — exact NN via 1-D binning.
// K1: for each of 16 arrays (8 batches x {x,tgt}), histogram points into 256
//     x-bins over [-6,6], prefix-sum, scatter into g_sorted (sorted by bin).
// K2: for each (b,dir) pair, each thread owns one query (iterated in SORTED
//     order -> warp lanes share bins). Scan own bin, expand L/R, stop a side
//     when (qx - edge)^2 >= best. Exact min (lower bound is conservative).
//     sqrt + block reduce + atomicAdd.

#define NPTS    4096
#define THREADS 256
#define NBINS   256
#define NARR    16
#define RANGE_LO (-6.0f)
#define RANGE_W  (12.0f / NBINS)
#define INV_W    (NBINS / 12.0f)

__device__ float2 g_sorted[NARR][NPTS];     // 512 KB
__device__ int    g_start[NARR][NBINS + 1];

// ---------------- K1: bin + scatter (16 blocks) ----------------
__global__ __launch_bounds__(THREADS)
void bin_kernel(const float* __restrict__ x, const float* __restrict__ tgt)
{
    __shared__ int s_cnt[NBINS];
    __shared__ int s_start[NBINS + 1];

    const int a    = blockIdx.x;            // array id: b*2 + side
    const int side = a & 1;
    const int b    = a >> 1;
    const float2* src = (const float2*)((side ? tgt : x) + (size_t)b * NPTS * 2);

    s_cnt[threadIdx.x] = 0;
    __syncthreads();

    float2 pts[NPTS / THREADS];
    int    bins[NPTS / THREADS];
    #pragma unroll
    for (int k = 0; k < NPTS / THREADS; k++) {
        float2 p = src[k * THREADS + threadIdx.x];
        int bi = (int)floorf((p.x - RANGE_LO) * INV_W);
        bi = max(0, min(NBINS - 1, bi));
        pts[k] = p;
        bins[k] = bi;
        atomicAdd(&s_cnt[bi], 1);
    }
    __syncthreads();

    // Exclusive prefix sum of 256 counts: warp 0, 8 values per lane.
    if (threadIdx.x < 32) {
        int lane = threadIdx.x;
        int v[8], tot = 0;
        #pragma unroll
        for (int j = 0; j < 8; j++) { v[j] = s_cnt[lane * 8 + j]; tot += v[j]; }
        // exclusive scan of per-lane totals
        int excl = 0;
        #pragma unroll
        for (int off = 1; off < 32; off <<= 1) {
            int n = __shfl_up_sync(0xFFFFFFFFu, tot, off);
            if (lane >= off) tot += n;
        }
        excl = tot - (v[0] + v[1] + v[2] + v[3] + v[4] + v[5] + v[6] + v[7]);
        #pragma unroll
        for (int j = 0; j < 8; j++) {
            s_start[lane * 8 + j] = excl;
            excl += v[j];
        }
        if (lane == 31) s_start[NBINS] = NPTS;
    }
    __syncthreads();

    g_start[a][threadIdx.x] = s_start[threadIdx.x];
    if (threadIdx.x == 0) g_start[a][NBINS] = NPTS;

    // scatter cursors
    s_cnt[threadIdx.x] = s_start[threadIdx.x];
    __syncthreads();

    #pragma unroll
    for (int k = 0; k < NPTS / THREADS; k++) {
        int off = atomicAdd(&s_cnt[bins[k]], 1);
        g_sorted[a][off] = pts[k];
    }
}

// ---------------- K2: query (256 blocks) ----------------
#define QCHUNKS (NPTS / THREADS)   // 16

__global__ __launch_bounds__(THREADS)
void query_kernel(float* __restrict__ out)
{
    __shared__ __align__(16) float2 s_db[NPTS];    // 32 KB
    __shared__ int   s_s[NBINS + 1];
    __shared__ float s_warp[THREADS / 32];

    const int chunk = blockIdx.x & (QCHUNKS - 1);
    const int pair  = blockIdx.x >> 4;      // 0..15
    const int dir   = pair & 1;
    const int b     = pair >> 1;
    const int qa    = b * 2 + dir;          // query array
    const int da    = b * 2 + (dir ^ 1);    // DB array

    // Stage sorted DB + bin starts.
    {
        const float4* p4 = (const float4*)g_sorted[da];
        float4* d4 = (float4*)s_db;
        #pragma unroll
        for (int k = 0; k < NPTS / 2 / THREADS; k++)
            d4[k * THREADS + threadIdx.x] = p4[k * THREADS + threadIdx.x];
        for (int i = threadIdx.x; i < NBINS + 1; i += THREADS)
            s_s[i] = g_start[da][i];
    }
    __syncthreads();

    const int qi = chunk * THREADS + threadIdx.x;
    const float2 q = g_sorted[qa][qi];      // sorted order -> coherent lanes

    int qb = (int)floorf((q.x - RANGE_LO) * INV_W);
    qb = max(0, min(NBINS - 1, qb));

    float best = CUDART_INF_F;

    // scan own bin
    {
        int j = s_s[qb], e = s_s[qb + 1];
        for (; j < e; j++) {
            float2 t = s_db[j];
            float dx = t.x - q.x;
            float dy = t.y - q.y;
            best = fminf(best, fmaf(dx, dx, dy * dy));
        }
    }

    int  L = qb - 1, R = qb + 1;
    bool goL = (L >= 0), goR = (R < NBINS);
    while (goL || goR) {
        if (goL) {
            float e = q.x - (RANGE_LO + (float)(L + 1) * RANGE_W);
            if (e * e < best) {
                int j = s_s[L], je = s_s[L + 1];
                for (; j < je; j++) {
                    float2 t = s_db[j];
                    float dx = t.x - q.x;
                    float dy = t.y - q.y;
                    best = fminf(best, fmaf(dx, dx, dy * dy));
                }
                L--; goL = (L >= 0);
            } else goL = false;
        }
        if (goR) {
            float e = (RANGE_LO + (float)R * RANGE_W) - q.x;
            if (e * e < best) {
                int j = s_s[R], je = s_s[R + 1];
                for (; j < je; j++) {
                    float2 t = s_db[j];
                    float dx = t.x - q.x;
                    float dy = t.y - q.y;
                    best = fminf(best, fmaf(dx, dx, dy * dy));
                }
                R++; goR = (R < NBINS);
            } else goR = false;
        }
    }

    float v = sqrtf(best);

    // block reduce + atomic
    #pragma unroll
    for (int off = 16; off > 0; off >>= 1)
        v += __shfl_down_sync(0xFFFFFFFFu, v, off);
    const int lane = threadIdx.x & 31;
    const int wid  = threadIdx.x >> 5;
    if (lane == 0) s_warp[wid] = v;
    __syncthreads();
    if (wid == 0) {
        float w = (lane < THREADS / 32) ? s_warp[lane] : 0.0f;
        #pragma unroll
        for (int off = 4; off > 0; off >>= 1)
            w += __shfl_down_sync(0xFFFFFFFFu, w, off);
        if (lane == 0)
            atomicAdd(out, w * (1.0f / 32768.0f));
    }
}

extern "C" void kernel_launch(void* const* d_in, const int* in_sizes, int n_in,
                              void* d_out, int out_size)
{
    const float* x   = (const float*)d_in[0];   // [8,4096,2] f32
    const float* tgt = (const float*)d_in[1];   // [8,4096,2] f32
    float* out = (float*)d_out;

    (void)in_sizes; (void)n_in; (void)out_size;

    cudaMemsetAsync(d_out, 0, sizeof(float));
    bin_kernel<<<NARR, THREADS>>>(x, tgt);
    query_kernel<<<NARR * QCHUNKS, THREADS>>>(out);
}